// round 2
// baseline (speedup 1.0000x reference)
#include <cuda_runtime.h>

// Problem constants
namespace {
constexpr int kB   = 64;
constexpr int kS   = 128;
constexpr int kL   = 512;
constexpr int kVEC = 512;
constexpr int kHID = 1024;
constexpr int kRows = kB * kS;          // 8192
constexpr int kOut  = kVEC + kHID;      // 1536
}

// Scratch (no allocations allowed -> device globals)
__device__ float g_Q[(size_t)kRows * kHID];   // 33.5 MB
__device__ float g_P[(size_t)kRows * kL];     // 16.7 MB (scores, then attn in place)
__device__ int   g_is64;

// ---------------------------------------------------------------------------
// Probe: detect whether `skills` is int64 or int32.
// If int64 (little-endian), every odd 32-bit word is the high word of a value
// < 20001 -> zero. If int32, odd words are random values in [0, 20001): the
// probability all 64 sampled are zero is ~(1/20001)^64 ~= 0.
// ---------------------------------------------------------------------------
__global__ void probe_kernel(const int* __restrict__ s32) {
    int any = 0;
    for (int i = 1; i < 128; i += 2) any |= s32[i];
    g_is64 = (any == 0) ? 1 : 0;
}

__device__ __forceinline__ int skill_at(const int* __restrict__ s32, int row) {
    return g_is64 ? s32[2 * row] : s32[row];
}

// ---------------------------------------------------------------------------
// Gather sk rows into out[:, 0:512]
// ---------------------------------------------------------------------------
__global__ void gather_kernel(const int* __restrict__ s32,
                              const float* __restrict__ emb,
                              float* __restrict__ out) {
    const int row = blockIdx.x;
    const int idx = skill_at(s32, row);
    const float4* src = (const float4*)(emb + (size_t)idx * kVEC);
    float4* dst = (float4*)(out + (size_t)row * kOut);
    dst[threadIdx.x] = src[threadIdx.x];   // 128 threads * float4 = 512 floats
}

// ---------------------------------------------------------------------------
// GEMM1: Q[8192,1024] = gather(emb, skills)[8192,512] @ W[512,1024]
// Tile 128x64, BK=16, 256 threads, 8x4 micro-tile.
// ---------------------------------------------------------------------------
__global__ __launch_bounds__(256) void gemm1_kernel(const int* __restrict__ s32,
                                                    const float* __restrict__ emb,
                                                    const float* __restrict__ W) {
    __shared__ __align__(16) float As[16][132];   // [k][m], +4 pad
    __shared__ __align__(16) float Bs[16][68];    // [k][n], +4 pad
    __shared__ int sIdx[128];

    const int tid = threadIdx.x;
    const int m0 = blockIdx.y * 128;
    const int n0 = blockIdx.x * 64;

    if (tid < 128) sIdx[tid] = skill_at(s32, m0 + tid);
    __syncthreads();

    const int tm  = (tid >> 4) * 8;
    const int tn  = (tid & 15) * 4;
    const int ar  = tid >> 2;          // 0..63
    const int akq = (tid & 3) * 4;     // 0,4,8,12
    const int bk  = tid >> 4;          // 0..15
    const int bn  = (tid & 15) * 4;

    float acc[8][4] = {};

    for (int k0 = 0; k0 < kVEC; k0 += 16) {
#pragma unroll
        for (int it = 0; it < 2; ++it) {
            const int r = ar + it * 64;
            float4 v = *(const float4*)(emb + (size_t)sIdx[r] * kVEC + k0 + akq);
            As[akq + 0][r] = v.x; As[akq + 1][r] = v.y;
            As[akq + 2][r] = v.z; As[akq + 3][r] = v.w;
        }
        *(float4*)&Bs[bk][bn] =
            *(const float4*)(W + (size_t)(k0 + bk) * kHID + n0 + bn);
        __syncthreads();
#pragma unroll
        for (int kk = 0; kk < 16; ++kk) {
            float4 a0 = *(const float4*)&As[kk][tm];
            float4 a1 = *(const float4*)&As[kk][tm + 4];
            float4 b0 = *(const float4*)&Bs[kk][tn];
            const float a[8] = {a0.x, a0.y, a0.z, a0.w, a1.x, a1.y, a1.z, a1.w};
            const float b[4] = {b0.x, b0.y, b0.z, b0.w};
#pragma unroll
            for (int i = 0; i < 8; ++i)
#pragma unroll
                for (int j = 0; j < 4; ++j)
                    acc[i][j] = fmaf(a[i], b[j], acc[i][j]);
        }
        __syncthreads();
    }
#pragma unroll
    for (int i = 0; i < 8; ++i)
        *(float4*)(g_Q + (size_t)(m0 + tm + i) * kHID + n0 + tn) =
            make_float4(acc[i][0], acc[i][1], acc[i][2], acc[i][3]);
}

// ---------------------------------------------------------------------------
// GEMM2 (NT, per batch): scores[b][s][l] = sum_h Q[b,s,h] * desc[b,l,h]
// Tile 64x64, BK=16, 256 threads, 4x4 micro-tile -> 1024 CTAs total.
// ---------------------------------------------------------------------------
__global__ __launch_bounds__(256) void gemm2_kernel(const float* __restrict__ desc) {
    __shared__ __align__(16) float As[16][68];
    __shared__ __align__(16) float Bs[16][68];

    const int tid = threadIdx.x;
    const int b  = blockIdx.z;
    const int m0 = blockIdx.y * 64;
    const int n0 = blockIdx.x * 64;

    const int tm = (tid >> 4) * 4;
    const int tn = (tid & 15) * 4;
    const int r  = tid >> 2;           // 0..63
    const int kq = (tid & 3) * 4;

    const float* Qb = g_Q + (size_t)b * kS * kHID;
    const float* Db = desc + (size_t)b * kL * kHID;

    float acc[4][4] = {};

    for (int k0 = 0; k0 < kHID; k0 += 16) {
        {
            float4 v = *(const float4*)(Qb + (size_t)(m0 + r) * kHID + k0 + kq);
            As[kq + 0][r] = v.x; As[kq + 1][r] = v.y;
            As[kq + 2][r] = v.z; As[kq + 3][r] = v.w;
        }
        {
            float4 v = *(const float4*)(Db + (size_t)(n0 + r) * kHID + k0 + kq);
            Bs[kq + 0][r] = v.x; Bs[kq + 1][r] = v.y;
            Bs[kq + 2][r] = v.z; Bs[kq + 3][r] = v.w;
        }
        __syncthreads();
#pragma unroll
        for (int kk = 0; kk < 16; ++kk) {
            float4 a0 = *(const float4*)&As[kk][tm];
            float4 b0 = *(const float4*)&Bs[kk][tn];
            const float a[4] = {a0.x, a0.y, a0.z, a0.w};
            const float bb[4] = {b0.x, b0.y, b0.z, b0.w};
#pragma unroll
            for (int i = 0; i < 4; ++i)
#pragma unroll
                for (int j = 0; j < 4; ++j)
                    acc[i][j] = fmaf(a[i], bb[j], acc[i][j]);
        }
        __syncthreads();
    }
#pragma unroll
    for (int i = 0; i < 4; ++i)
        *(float4*)(g_P + (size_t)(b * kS + m0 + tm + i) * kL + n0 + tn) =
            make_float4(acc[i][0], acc[i][1], acc[i][2], acc[i][3]);
}

// ---------------------------------------------------------------------------
// Softmax over rows of g_P (8192 rows x 512). One warp per row.
// ---------------------------------------------------------------------------
__global__ void softmax_kernel() {
    const int lane = threadIdx.x & 31;
    const int warp = threadIdx.x >> 5;
    const int row = blockIdx.x * 8 + warp;
    float4* p = (float4*)(g_P + (size_t)row * kL);

    float4 v[4];
    float mx = -1e30f;
#pragma unroll
    for (int i = 0; i < 4; ++i) {
        v[i] = p[lane + 32 * i];
        mx = fmaxf(mx, fmaxf(fmaxf(v[i].x, v[i].y), fmaxf(v[i].z, v[i].w)));
    }
#pragma unroll
    for (int o = 16; o; o >>= 1) mx = fmaxf(mx, __shfl_xor_sync(0xffffffffu, mx, o));

    float sum = 0.f;
#pragma unroll
    for (int i = 0; i < 4; ++i) {
        v[i].x = __expf(v[i].x - mx); sum += v[i].x;
        v[i].y = __expf(v[i].y - mx); sum += v[i].y;
        v[i].z = __expf(v[i].z - mx); sum += v[i].z;
        v[i].w = __expf(v[i].w - mx); sum += v[i].w;
    }
#pragma unroll
    for (int o = 16; o; o >>= 1) sum += __shfl_xor_sync(0xffffffffu, sum, o);

    const float inv = 1.0f / sum;
#pragma unroll
    for (int i = 0; i < 4; ++i) {
        v[i].x *= inv; v[i].y *= inv; v[i].z *= inv; v[i].w *= inv;
        p[lane + 32 * i] = v[i];
    }
}

// ---------------------------------------------------------------------------
// GEMM3 (NN, per batch): ctx[b][s][h] = sum_l attn[b,s,l] * desc[b,l,h]
// Tile 128x64, BK=16, 256 threads, 8x4 micro-tile. Writes out[:, 512:1536].
// ---------------------------------------------------------------------------
__global__ __launch_bounds__(256) void gemm3_kernel(const float* __restrict__ desc,
                                                    float* __restrict__ out) {
    __shared__ __align__(16) float As[16][132];
    __shared__ __align__(16) float Bs[16][68];

    const int tid = threadIdx.x;
    const int b  = blockIdx.z;
    const int n0 = blockIdx.x * 64;

    const int tm  = (tid >> 4) * 8;
    const int tn  = (tid & 15) * 4;
    const int ar  = tid >> 2;
    const int akq = (tid & 3) * 4;
    const int bk  = tid >> 4;
    const int bn  = (tid & 15) * 4;

    const float* Pb = g_P + (size_t)b * kS * kL;
    const float* Db = desc + (size_t)b * kL * kHID;

    float acc[8][4] = {};

    for (int k0 = 0; k0 < kL; k0 += 16) {
#pragma unroll
        for (int it = 0; it < 2; ++it) {
            const int r = ar + it * 64;
            float4 v = *(const float4*)(Pb + (size_t)r * kL + k0 + akq);
            As[akq + 0][r] = v.x; As[akq + 1][r] = v.y;
            As[akq + 2][r] = v.z; As[akq + 3][r] = v.w;
        }
        *(float4*)&Bs[bk][bn] =
            *(const float4*)(Db + (size_t)(k0 + bk) * kHID + n0 + bn);
        __syncthreads();
#pragma unroll
        for (int kk = 0; kk < 16; ++kk) {
            float4 a0 = *(const float4*)&As[kk][tm];
            float4 a1 = *(const float4*)&As[kk][tm + 4];
            float4 b0 = *(const float4*)&Bs[kk][tn];
            const float a[8] = {a0.x, a0.y, a0.z, a0.w, a1.x, a1.y, a1.z, a1.w};
            const float bb[4] = {b0.x, b0.y, b0.z, b0.w};
#pragma unroll
            for (int i = 0; i < 8; ++i)
#pragma unroll
                for (int j = 0; j < 4; ++j)
                    acc[i][j] = fmaf(a[i], bb[j], acc[i][j]);
        }
        __syncthreads();
    }
#pragma unroll
    for (int i = 0; i < 8; ++i)
        *(float4*)(out + (size_t)(b * kS + tm + i) * kOut + kVEC + n0 + tn) =
            make_float4(acc[i][0], acc[i][1], acc[i][2], acc[i][3]);
}

// ---------------------------------------------------------------------------
// Launch
// ---------------------------------------------------------------------------
extern "C" void kernel_launch(void* const* d_in, const int* in_sizes, int n_in,
                              void* d_out, int out_size) {
    (void)in_sizes; (void)n_in; (void)out_size;
    const int*   s32  = (const int*)d_in[0];    // skills (int64 or int32, probed)
    const float* desc = (const float*)d_in[1];  // [B, L, HID]
    const float* emb  = (const float*)d_in[2];  // [VOCAB, VEC]
    const float* W    = (const float*)d_in[3];  // [VEC, HID]
    float* out = (float*)d_out;                 // [B, S*(VEC+HID)]

    probe_kernel<<<1, 1>>>(s32);
    gather_kernel<<<kRows, 128>>>(s32, emb, out);

    { dim3 g(kHID / 64, kRows / 128); gemm1_kernel<<<g, 256>>>(s32, emb, W); }
    { dim3 g(kL / 64, kS / 64, kB);   gemm2_kernel<<<g, 256>>>(desc); }
    softmax_kernel<<<kRows / 8, 256>>>();
    { dim3 g(kHID / 64, 1, kB);       gemm3_kernel<<<g, 256>>>(desc, out); }
}

// round 4
// speedup vs baseline: 1.3536x; 1.3536x over previous
#include <cuda_runtime.h>
#include <cuda_bf16.h>
#include <cstdint>

// ---------------------------------------------------------------------------
// Problem constants
// ---------------------------------------------------------------------------
namespace {
constexpr int kB   = 64;
constexpr int kS   = 128;
constexpr int kL   = 512;
constexpr int kVEC = 512;
constexpr int kHID = 1024;
constexpr int kRows = kB * kS;          // 8192
constexpr int kOut  = kVEC + kHID;      // 1536

// MMA kernel tiling
constexpr int OFF_AHI = 0;
constexpr int OFF_ALO = 16384;
constexpr int OFF_BHI = 32768;
constexpr int OFF_BLO = 49152;
constexpr int SMEM_BYTES = 65536;
}

// ---------------------------------------------------------------------------
// Device-global scratch (no allocations allowed)
// ---------------------------------------------------------------------------
#define DEVB __device__ __align__(16)
DEVB __nv_bfloat16 g_SKhi[(size_t)kRows * kVEC];
DEVB __nv_bfloat16 g_SKlo[(size_t)kRows * kVEC];
DEVB __nv_bfloat16 g_Wthi[(size_t)kHID * kVEC];        // W^T [1024,512]
DEVB __nv_bfloat16 g_Wtlo[(size_t)kHID * kVEC];
DEVB __nv_bfloat16 g_Dhi [(size_t)kB * kL * kHID];     // desc  [b][l][h]
DEVB __nv_bfloat16 g_Dlo [(size_t)kB * kL * kHID];
DEVB __nv_bfloat16 g_DThi[(size_t)kB * kHID * kL];     // desc^T [b][h][l]
DEVB __nv_bfloat16 g_DTlo[(size_t)kB * kHID * kL];
DEVB __nv_bfloat16 g_Qhi [(size_t)kRows * kHID];
DEVB __nv_bfloat16 g_Qlo [(size_t)kRows * kHID];
DEVB float         g_P   [(size_t)kRows * kL];         // scores (fp32)
DEVB __nv_bfloat16 g_Phi [(size_t)kRows * kL];         // attn split
DEVB __nv_bfloat16 g_Plo [(size_t)kRows * kL];
__device__ int g_is64;

// ---------------------------------------------------------------------------
// Helpers
// ---------------------------------------------------------------------------
__device__ __forceinline__ uint32_t smem_u32(const void* p) {
    uint32_t a;
    asm("{ .reg .u64 t; cvta.to.shared.u64 t, %1; cvt.u32.u64 %0, t; }"
        : "=r"(a) : "l"(p));
    return a;
}
__device__ __forceinline__ uint32_t sw128(uint32_t off) {
    return off ^ ((off >> 3) & 0x70);
}
__device__ __forceinline__ void ldsm_x4(uint32_t* r, uint32_t addr) {
    asm volatile("ldmatrix.sync.aligned.m8n8.x4.shared.b16 {%0,%1,%2,%3}, [%4];"
                 : "=r"(r[0]), "=r"(r[1]), "=r"(r[2]), "=r"(r[3]) : "r"(addr));
}
__device__ __forceinline__ void mma_bf16(float* c, const uint32_t* a, const uint32_t* b) {
    asm volatile(
        "mma.sync.aligned.m16n8k16.row.col.f32.bf16.bf16.f32 "
        "{%0,%1,%2,%3}, {%4,%5,%6,%7}, {%8,%9}, {%0,%1,%2,%3};"
        : "+f"(c[0]), "+f"(c[1]), "+f"(c[2]), "+f"(c[3])
        : "r"(a[0]), "r"(a[1]), "r"(a[2]), "r"(a[3]), "r"(b[0]), "r"(b[1]));
}
__device__ __forceinline__ void split2(float v, __nv_bfloat16& h, __nv_bfloat16& l) {
    h = __float2bfloat16(v);
    l = __float2bfloat16(v - __bfloat162float(h));
}

// ---------------------------------------------------------------------------
// Probe int64 vs int32 skills
// ---------------------------------------------------------------------------
__global__ void probe_kernel(const int* __restrict__ s32) {
    int any = 0;
    for (int i = 1; i < 128; i += 2) any |= s32[i];
    g_is64 = (any == 0) ? 1 : 0;
}
__device__ __forceinline__ int skill_at(const int* __restrict__ s32, int row) {
    return g_is64 ? s32[2 * row] : s32[row];
}

// ---------------------------------------------------------------------------
// conv_sk: gather emb rows -> out[:,0:512] fp32 AND g_SKhi/lo bf16 split
// ---------------------------------------------------------------------------
__global__ void conv_sk(const int* __restrict__ s32,
                        const float* __restrict__ emb,
                        float* __restrict__ out) {
    const int row = blockIdx.x;
    const int idx = skill_at(s32, row);
    const int tx = threadIdx.x;               // 128 threads, 4 floats each
    float4 v = ((const float4*)(emb + (size_t)idx * kVEC))[tx];
    ((float4*)(out + (size_t)row * kOut))[tx] = v;

    __nv_bfloat16 h0, h1, h2, h3, l0, l1, l2, l3;
    split2(v.x, h0, l0); split2(v.y, h1, l1);
    split2(v.z, h2, l2); split2(v.w, h3, l3);
    size_t o = (size_t)row * kVEC + tx * 4;
    __nv_bfloat162 a; a.x = h0; a.y = h1; *(__nv_bfloat162*)(g_SKhi + o) = a;
    a.x = h2; a.y = h3; *(__nv_bfloat162*)(g_SKhi + o + 2) = a;
    a.x = l0; a.y = l1; *(__nv_bfloat162*)(g_SKlo + o) = a;
    a.x = l2; a.y = l3; *(__nv_bfloat162*)(g_SKlo + o + 2) = a;
}

// ---------------------------------------------------------------------------
// conv_desc: split desc -> g_Dhi/lo AND transposed -> g_DThi/lo. 32x32 tiles.
// ---------------------------------------------------------------------------
__global__ void conv_desc(const float* __restrict__ desc) {
    __shared__ float t[32][33];
    const int b = blockIdx.z, h0 = blockIdx.x * 32, l0 = blockIdx.y * 32;
    const int tx = threadIdx.x, ty = threadIdx.y;
    const float* D = desc + (size_t)b * kL * kHID;
    const size_t baseD  = (size_t)b * kL * kHID;
    const size_t baseDT = (size_t)b * kHID * kL;
#pragma unroll
    for (int i = 0; i < 4; ++i) {
        int l = l0 + ty + 8 * i;
        float v = D[(size_t)l * kHID + h0 + tx];
        t[ty + 8 * i][tx] = v;
        __nv_bfloat16 h, lo; split2(v, h, lo);
        g_Dhi[baseD + (size_t)l * kHID + h0 + tx] = h;
        g_Dlo[baseD + (size_t)l * kHID + h0 + tx] = lo;
    }
    __syncthreads();
#pragma unroll
    for (int i = 0; i < 4; ++i) {
        int h = h0 + ty + 8 * i;
        float v = t[tx][ty + 8 * i];
        __nv_bfloat16 hh, lo; split2(v, hh, lo);
        g_DThi[baseDT + (size_t)h * kL + l0 + tx] = hh;
        g_DTlo[baseDT + (size_t)h * kL + l0 + tx] = lo;
    }
}

// ---------------------------------------------------------------------------
// conv_W: transpose+split W[512,1024] -> Wt[1024,512] hi/lo
// ---------------------------------------------------------------------------
__global__ void conv_W(const float* __restrict__ W) {
    __shared__ float t[32][33];
    const int n0 = blockIdx.x * 32, k0 = blockIdx.y * 32;
    const int tx = threadIdx.x, ty = threadIdx.y;
#pragma unroll
    for (int i = 0; i < 4; ++i) {
        int k = k0 + ty + 8 * i;
        t[ty + 8 * i][tx] = W[(size_t)k * kHID + n0 + tx];
    }
    __syncthreads();
#pragma unroll
    for (int i = 0; i < 4; ++i) {
        int n = n0 + ty + 8 * i;
        float v = t[tx][ty + 8 * i];
        __nv_bfloat16 h, lo; split2(v, h, lo);
        g_Wthi[(size_t)n * kVEC + k0 + tx] = h;
        g_Wtlo[(size_t)n * kVEC + k0 + tx] = lo;
    }
}

// ---------------------------------------------------------------------------
// Split-bf16 warp-MMA GEMM (mma.sync m16n8k16, HMMA on tensor pipe).
// CTA tile 128x128, K-chunk 64. 8 warps, warp grid 4(M) x 2(N), warp tile 32x64.
// All B operands stored [n][k] (K contiguous) = col-major KxN -> "row.col" mma.
// 3 accumulating products per k-step: Ahi*Bhi + Ahi*Blo + Alo*Bhi.
// MODE 1: Q = SK @ Wt^T    (out: split bf16 g_Qhi/lo, ld kHID)
// MODE 2: P = Q @ desc^T   (out: fp32 g_P, ld kL)
// MODE 3: ctx = attn @ DT^T (out: fp32 out[., 512+n], ld kOut)
// ---------------------------------------------------------------------------
template<int MODE>
__global__ __launch_bounds__(256) void mma_gemm(float* __restrict__ outP) {
    extern __shared__ __align__(1024) char smem[];
    const uint32_t sb = smem_u32(smem);
    const int tid = threadIdx.x, wid = tid >> 5, lane = tid & 31;
    const int x = blockIdx.x, y = blockIdx.y;

    constexpr int K = (MODE == 2) ? kHID : kVEC;

    const __nv_bfloat16 *Ahi, *Alo, *Bhi, *Blo;
    if (MODE == 1) {
        Ahi = g_SKhi + (size_t)y * 128 * K;  Alo = g_SKlo + (size_t)y * 128 * K;
        Bhi = g_Wthi + (size_t)x * 128 * K;  Blo = g_Wtlo + (size_t)x * 128 * K;
    } else if (MODE == 2) {
        Ahi = g_Qhi + (size_t)y * 128 * K;   Alo = g_Qlo + (size_t)y * 128 * K;
        Bhi = g_Dhi + (size_t)y * kL * kHID + (size_t)x * 128 * K;
        Blo = g_Dlo + (size_t)y * kL * kHID + (size_t)x * 128 * K;
    } else {
        Ahi = g_Phi + (size_t)y * 128 * K;   Alo = g_Plo + (size_t)y * 128 * K;
        Bhi = g_DThi + (size_t)y * kHID * kL + (size_t)x * 128 * K;
        Blo = g_DTlo + (size_t)y * kHID * kL + (size_t)x * 128 * K;
    }

    const int wm = (wid >> 1) * 32;       // warp M base in CTA tile
    const int wn = (wid & 1) * 64;        // warp N base in CTA tile

    float acc[2][8][4] = {};

    for (int k0 = 0; k0 < K; k0 += 64) {
        // Load 4 tiles of [128 rows x 64 bf16] (128B rows, SW128 swizzle).
#pragma unroll
        for (int it = 0; it < 4; ++it) {
            const int ch = tid + it * 256;
            const int r = ch >> 3, c = ch & 7;
            const uint32_t d = sw128((uint32_t)(r * 128 + c * 16));
            const size_t so = (size_t)r * K + k0 + c * 8;
            *(uint4*)(smem + OFF_AHI + d) = *(const uint4*)(Ahi + so);
            *(uint4*)(smem + OFF_ALO + d) = *(const uint4*)(Alo + so);
            *(uint4*)(smem + OFF_BHI + d) = *(const uint4*)(Bhi + so);
            *(uint4*)(smem + OFF_BLO + d) = *(const uint4*)(Blo + so);
        }
        __syncthreads();

#pragma unroll
        for (int kk = 0; kk < 4; ++kk) {      // k-steps of 16 bf16 (32 bytes)
            uint32_t aHi[2][4], aLo[2][4], bHi[8][2], bLo[8][2];
            // A fragments: ldmatrix.x4 per 16-row m-tile
#pragma unroll
            for (int i = 0; i < 2; ++i) {
                const int row = wm + i * 16 + (lane & 15);
                const int kb  = kk * 32 + (lane >> 4) * 16;
                const uint32_t d = sw128((uint32_t)(row * 128 + kb));
                ldsm_x4(aHi[i], sb + OFF_AHI + d);
                ldsm_x4(aLo[i], sb + OFF_ALO + d);
            }
            // B fragments: ldmatrix.x4 per 16-n group (4 groups -> 64 n)
#pragma unroll
            for (int j4 = 0; j4 < 4; ++j4) {
                const int row = wn + j4 * 16 + ((lane >> 4) & 1) * 8 + (lane & 7);
                const int kb  = kk * 32 + ((lane >> 3) & 1) * 16;
                const uint32_t d = sw128((uint32_t)(row * 128 + kb));
                uint32_t r4[4];
                ldsm_x4(r4, sb + OFF_BHI + d);
                bHi[j4 * 2][0] = r4[0]; bHi[j4 * 2][1] = r4[1];
                bHi[j4 * 2 + 1][0] = r4[2]; bHi[j4 * 2 + 1][1] = r4[3];
                ldsm_x4(r4, sb + OFF_BLO + d);
                bLo[j4 * 2][0] = r4[0]; bLo[j4 * 2][1] = r4[1];
                bLo[j4 * 2 + 1][0] = r4[2]; bLo[j4 * 2 + 1][1] = r4[3];
            }
#pragma unroll
            for (int i = 0; i < 2; ++i)
#pragma unroll
                for (int j = 0; j < 8; ++j) {
                    mma_bf16(acc[i][j], aHi[i], bHi[j]);
                    mma_bf16(acc[i][j], aHi[i], bLo[j]);
                    mma_bf16(acc[i][j], aLo[i], bHi[j]);
                }
        }
        __syncthreads();
    }

    // Epilogue. Thread holds rows (g, g+8), cols (2*t4, 2*t4+1) per mma tile.
    const int g = lane >> 2, t4 = lane & 3;
#pragma unroll
    for (int i = 0; i < 2; ++i) {
#pragma unroll
        for (int j = 0; j < 8; ++j) {
            const int r0 = wm + i * 16 + g;
            const int r1 = r0 + 8;
            const int cc = wn + j * 8 + 2 * t4;
            if (MODE == 1) {
                const size_t o0 = (size_t)(y * 128 + r0) * kHID + x * 128 + cc;
                const size_t o1 = (size_t)(y * 128 + r1) * kHID + x * 128 + cc;
                __nv_bfloat16 h0, l0, h1, l1;
                split2(acc[i][j][0], h0, l0); split2(acc[i][j][1], h1, l1);
                __nv_bfloat162 ph, pl;
                ph.x = h0; ph.y = h1; pl.x = l0; pl.y = l1;
                *(__nv_bfloat162*)(g_Qhi + o0) = ph;
                *(__nv_bfloat162*)(g_Qlo + o0) = pl;
                split2(acc[i][j][2], h0, l0); split2(acc[i][j][3], h1, l1);
                ph.x = h0; ph.y = h1; pl.x = l0; pl.y = l1;
                *(__nv_bfloat162*)(g_Qhi + o1) = ph;
                *(__nv_bfloat162*)(g_Qlo + o1) = pl;
            } else {
                float* o0;
                float* o1;
                if (MODE == 2) {
                    o0 = g_P + (size_t)(y * 128 + r0) * kL + x * 128 + cc;
                    o1 = g_P + (size_t)(y * 128 + r1) * kL + x * 128 + cc;
                } else {
                    o0 = outP + (size_t)(y * 128 + r0) * kOut + kVEC + x * 128 + cc;
                    o1 = outP + (size_t)(y * 128 + r1) * kOut + kVEC + x * 128 + cc;
                }
                *(float2*)o0 = make_float2(acc[i][j][0], acc[i][j][1]);
                *(float2*)o1 = make_float2(acc[i][j][2], acc[i][j][3]);
            }
        }
    }
}

// ---------------------------------------------------------------------------
// Softmax over rows of g_P (8192 x 512) -> split bf16 attn g_Phi/g_Plo
// ---------------------------------------------------------------------------
__global__ void softmax_kernel() {
    const int lane = threadIdx.x & 31;
    const int warp = threadIdx.x >> 5;
    const int row = blockIdx.x * 8 + warp;
    const float4* p = (const float4*)(g_P + (size_t)row * kL);

    float4 v[4];
    float mx = -1e30f;
#pragma unroll
    for (int i = 0; i < 4; ++i) {
        v[i] = p[lane + 32 * i];
        mx = fmaxf(mx, fmaxf(fmaxf(v[i].x, v[i].y), fmaxf(v[i].z, v[i].w)));
    }
#pragma unroll
    for (int o = 16; o; o >>= 1) mx = fmaxf(mx, __shfl_xor_sync(0xffffffffu, mx, o));

    float sum = 0.f;
#pragma unroll
    for (int i = 0; i < 4; ++i) {
        v[i].x = __expf(v[i].x - mx); sum += v[i].x;
        v[i].y = __expf(v[i].y - mx); sum += v[i].y;
        v[i].z = __expf(v[i].z - mx); sum += v[i].z;
        v[i].w = __expf(v[i].w - mx); sum += v[i].w;
    }
#pragma unroll
    for (int o = 16; o; o >>= 1) sum += __shfl_xor_sync(0xffffffffu, sum, o);

    const float inv = 1.0f / sum;
#pragma unroll
    for (int i = 0; i < 4; ++i) {
        float e[4] = {v[i].x * inv, v[i].y * inv, v[i].z * inv, v[i].w * inv};
        size_t o = (size_t)row * kL + 4 * (lane + 32 * i);
        __nv_bfloat16 h0, h1, h2, h3, l0, l1, l2, l3;
        split2(e[0], h0, l0); split2(e[1], h1, l1);
        split2(e[2], h2, l2); split2(e[3], h3, l3);
        __nv_bfloat162 a;
        a.x = h0; a.y = h1; *(__nv_bfloat162*)(g_Phi + o) = a;
        a.x = h2; a.y = h3; *(__nv_bfloat162*)(g_Phi + o + 2) = a;
        a.x = l0; a.y = l1; *(__nv_bfloat162*)(g_Plo + o) = a;
        a.x = l2; a.y = l3; *(__nv_bfloat162*)(g_Plo + o + 2) = a;
    }
}

// ---------------------------------------------------------------------------
// Launch
// ---------------------------------------------------------------------------
extern "C" void kernel_launch(void* const* d_in, const int* in_sizes, int n_in,
                              void* d_out, int out_size) {
    (void)in_sizes; (void)n_in; (void)out_size;
    const int*   s32  = (const int*)d_in[0];
    const float* desc = (const float*)d_in[1];
    const float* emb  = (const float*)d_in[2];
    const float* W    = (const float*)d_in[3];
    float* out = (float*)d_out;

    cudaFuncSetAttribute(mma_gemm<1>, cudaFuncAttributeMaxDynamicSharedMemorySize, SMEM_BYTES);
    cudaFuncSetAttribute(mma_gemm<2>, cudaFuncAttributeMaxDynamicSharedMemorySize, SMEM_BYTES);
    cudaFuncSetAttribute(mma_gemm<3>, cudaFuncAttributeMaxDynamicSharedMemorySize, SMEM_BYTES);

    probe_kernel<<<1, 1>>>(s32);
    conv_sk<<<kRows, 128>>>(s32, emb, out);
    conv_desc<<<dim3(kHID / 32, kL / 32, kB), dim3(32, 8)>>>(desc);
    conv_W<<<dim3(kHID / 32, kVEC / 32), dim3(32, 8)>>>(W);

    // GEMM1: Q[8192,1024]
    mma_gemm<1><<<dim3(kHID / 128, kRows / 128), 256, SMEM_BYTES>>>(nullptr);
    // GEMM2: scores[b][128,512]
    mma_gemm<2><<<dim3(kL / 128, kB), 256, SMEM_BYTES>>>(nullptr);
    softmax_kernel<<<kRows / 8, 256>>>();
    // GEMM3: ctx[b][128,1024]
    mma_gemm<3><<<dim3(kHID / 128, kB), 256, SMEM_BYTES>>>(out);
}

// round 5
// speedup vs baseline: 2.3077x; 1.7048x over previous
#include <cuda_runtime.h>
#include <cuda_bf16.h>
#include <cstdint>

// ---------------------------------------------------------------------------
// Problem constants
// ---------------------------------------------------------------------------
namespace {
constexpr int kB   = 64;
constexpr int kS   = 128;
constexpr int kL   = 512;
constexpr int kVEC = 512;
constexpr int kHID = 1024;
constexpr int kRows = kB * kS;          // 8192
constexpr int kOut  = kVEC + kHID;      // 1536

// MMA kernel smem layout (per stage)
constexpr int OFF_AHI = 0;
constexpr int OFF_ALO = 16384;
constexpr int OFF_BHI = 32768;
constexpr int OFF_BLO = 49152;
constexpr int STG_BYTES = 65536;
constexpr int SMEM_BYTES = 2 * STG_BYTES;   // 131072, double buffered
}

// ---------------------------------------------------------------------------
// Device-global scratch (no allocations allowed)
// ---------------------------------------------------------------------------
#define DEVB __device__ __align__(16)
DEVB __nv_bfloat16 g_SKhi[(size_t)kRows * kVEC];
DEVB __nv_bfloat16 g_SKlo[(size_t)kRows * kVEC];
DEVB __nv_bfloat16 g_Wthi[(size_t)kHID * kVEC];        // W^T [1024,512]
DEVB __nv_bfloat16 g_Wtlo[(size_t)kHID * kVEC];
DEVB __nv_bfloat16 g_Dhi [(size_t)kB * kL * kHID];     // desc [b][l][h]
DEVB __nv_bfloat16 g_Dlo [(size_t)kB * kL * kHID];
DEVB __nv_bfloat16 g_Qhi [(size_t)kRows * kHID];
DEVB __nv_bfloat16 g_Qlo [(size_t)kRows * kHID];
DEVB float         g_P   [(size_t)kRows * kL];         // scores (fp32)
DEVB __nv_bfloat16 g_Phi [(size_t)kRows * kL];         // attn split
DEVB __nv_bfloat16 g_Plo [(size_t)kRows * kL];
__device__ int g_is64;

// ---------------------------------------------------------------------------
// Helpers
// ---------------------------------------------------------------------------
__device__ __forceinline__ uint32_t smem_u32(const void* p) {
    uint32_t a;
    asm("{ .reg .u64 t; cvta.to.shared.u64 t, %1; cvt.u32.u64 %0, t; }"
        : "=r"(a) : "l"(p));
    return a;
}
// swizzle for 128B rows
__device__ __forceinline__ uint32_t sw128(uint32_t off) {
    return off ^ ((off >> 3) & 0x70);
}
// swizzle for 256B rows (trans-B tile): row bits 0-2 -> offset bits 4-6
__device__ __forceinline__ uint32_t sw256(uint32_t off) {
    return off ^ ((off >> 4) & 0x70);
}
__device__ __forceinline__ void ldsm_x4(uint32_t* r, uint32_t addr) {
    asm volatile("ldmatrix.sync.aligned.m8n8.x4.shared.b16 {%0,%1,%2,%3}, [%4];"
                 : "=r"(r[0]), "=r"(r[1]), "=r"(r[2]), "=r"(r[3]) : "r"(addr));
}
__device__ __forceinline__ void ldsm_x4_t(uint32_t* r, uint32_t addr) {
    asm volatile("ldmatrix.sync.aligned.m8n8.x4.trans.shared.b16 {%0,%1,%2,%3}, [%4];"
                 : "=r"(r[0]), "=r"(r[1]), "=r"(r[2]), "=r"(r[3]) : "r"(addr));
}
__device__ __forceinline__ void mma_bf16(float* c, const uint32_t* a, const uint32_t* b) {
    asm volatile(
        "mma.sync.aligned.m16n8k16.row.col.f32.bf16.bf16.f32 "
        "{%0,%1,%2,%3}, {%4,%5,%6,%7}, {%8,%9}, {%0,%1,%2,%3};"
        : "+f"(c[0]), "+f"(c[1]), "+f"(c[2]), "+f"(c[3])
        : "r"(a[0]), "r"(a[1]), "r"(a[2]), "r"(a[3]), "r"(b[0]), "r"(b[1]));
}
__device__ __forceinline__ void cpa16(uint32_t s, const void* g) {
    asm volatile("cp.async.cg.shared.global [%0], [%1], 16;" :: "r"(s), "l"(g));
}
__device__ __forceinline__ void cpa_commit() {
    asm volatile("cp.async.commit_group;" ::: "memory");
}
__device__ __forceinline__ void cpa_wait1() {
    asm volatile("cp.async.wait_group 1;" ::: "memory");
}
__device__ __forceinline__ void split2(float v, __nv_bfloat16& h, __nv_bfloat16& l) {
    h = __float2bfloat16(v);
    l = __float2bfloat16(v - __bfloat162float(h));
}

// ---------------------------------------------------------------------------
// Probe int64 vs int32 skills
// ---------------------------------------------------------------------------
__global__ void probe_kernel(const int* __restrict__ s32) {
    int any = 0;
    for (int i = 1; i < 128; i += 2) any |= s32[i];
    g_is64 = (any == 0) ? 1 : 0;
}
__device__ __forceinline__ int skill_at(const int* __restrict__ s32, int row) {
    return g_is64 ? s32[2 * row] : s32[row];
}

// ---------------------------------------------------------------------------
// conv_sk: gather emb rows -> out[:,0:512] fp32 AND g_SKhi/lo bf16 split
// ---------------------------------------------------------------------------
__global__ void conv_sk(const int* __restrict__ s32,
                        const float* __restrict__ emb,
                        float* __restrict__ out) {
    const int row = blockIdx.x;
    const int idx = skill_at(s32, row);
    const int tx = threadIdx.x;               // 128 threads, 4 floats each
    float4 v = ((const float4*)(emb + (size_t)idx * kVEC))[tx];
    ((float4*)(out + (size_t)row * kOut))[tx] = v;

    __nv_bfloat16 h0, h1, h2, h3, l0, l1, l2, l3;
    split2(v.x, h0, l0); split2(v.y, h1, l1);
    split2(v.z, h2, l2); split2(v.w, h3, l3);
    size_t o = (size_t)row * kVEC + tx * 4;
    __nv_bfloat162 a; a.x = h0; a.y = h1; *(__nv_bfloat162*)(g_SKhi + o) = a;
    a.x = h2; a.y = h3; *(__nv_bfloat162*)(g_SKhi + o + 2) = a;
    a.x = l0; a.y = l1; *(__nv_bfloat162*)(g_SKlo + o) = a;
    a.x = l2; a.y = l3; *(__nv_bfloat162*)(g_SKlo + o + 2) = a;
}

// ---------------------------------------------------------------------------
// conv_desc: elementwise split desc -> g_Dhi/g_Dlo (no transpose needed)
// ---------------------------------------------------------------------------
__global__ void conv_desc(const float* __restrict__ desc) {
    const size_t i = ((size_t)blockIdx.x * 256 + threadIdx.x) * 4;
    float4 v = *(const float4*)(desc + i);
    __nv_bfloat16 h0, h1, h2, h3, l0, l1, l2, l3;
    split2(v.x, h0, l0); split2(v.y, h1, l1);
    split2(v.z, h2, l2); split2(v.w, h3, l3);
    __nv_bfloat162 a;
    a.x = h0; a.y = h1; *(__nv_bfloat162*)(g_Dhi + i) = a;
    a.x = h2; a.y = h3; *(__nv_bfloat162*)(g_Dhi + i + 2) = a;
    a.x = l0; a.y = l1; *(__nv_bfloat162*)(g_Dlo + i) = a;
    a.x = l2; a.y = l3; *(__nv_bfloat162*)(g_Dlo + i + 2) = a;
}

// ---------------------------------------------------------------------------
// conv_W: transpose+split W[512,1024] -> Wt[1024,512] hi/lo
// ---------------------------------------------------------------------------
__global__ void conv_W(const float* __restrict__ W) {
    __shared__ float t[32][33];
    const int n0 = blockIdx.x * 32, k0 = blockIdx.y * 32;
    const int tx = threadIdx.x, ty = threadIdx.y;
#pragma unroll
    for (int i = 0; i < 4; ++i) {
        int k = k0 + ty + 8 * i;
        t[ty + 8 * i][tx] = W[(size_t)k * kHID + n0 + tx];
    }
    __syncthreads();
#pragma unroll
    for (int i = 0; i < 4; ++i) {
        int n = n0 + ty + 8 * i;
        float v = t[tx][ty + 8 * i];
        __nv_bfloat16 h, lo; split2(v, h, lo);
        g_Wthi[(size_t)n * kVEC + k0 + tx] = h;
        g_Wtlo[(size_t)n * kVEC + k0 + tx] = lo;
    }
}

// ---------------------------------------------------------------------------
// Split-bf16 warp-MMA GEMM (mma.sync m16n8k16), cp.async double-buffered.
// CTA tile 128x128, K-chunk 64, 8 warps (4M x 2N), warp tile 32x64.
// 3 accumulating products per k-step: Ahi*Bhi + Ahi*Blo + Alo*Bhi.
// MODE 1: Q = SK @ Wt^T     B [n][k] non-trans      (out: split bf16 Q)
// MODE 2: P = Q @ desc^T    B = desc [l][h]=[n][k]  (out: fp32 g_P)
// MODE 3: ctx = attn @ D    B = desc [l][h]=[k][n] via ldmatrix.trans
//                                                   (out: fp32 out[.,512+n])
// ---------------------------------------------------------------------------
template<int MODE>
__global__ __launch_bounds__(256, 1) void mma_gemm(float* __restrict__ outP) {
    extern __shared__ __align__(1024) char smem[];
    const uint32_t sb = smem_u32(smem);
    const int tid = threadIdx.x, wid = tid >> 5, lane = tid & 31;
    const int x = blockIdx.x, y = blockIdx.y;

    constexpr int K = (MODE == 2) ? kHID : kVEC;

    const __nv_bfloat16 *Ahi, *Alo, *Bhi, *Blo;
    if (MODE == 1) {
        Ahi = g_SKhi + (size_t)y * 128 * K;  Alo = g_SKlo + (size_t)y * 128 * K;
        Bhi = g_Wthi + (size_t)x * 128 * K;  Blo = g_Wtlo + (size_t)x * 128 * K;
    } else if (MODE == 2) {
        Ahi = g_Qhi + (size_t)y * 128 * K;   Alo = g_Qlo + (size_t)y * 128 * K;
        Bhi = g_Dhi + (size_t)y * kL * kHID + (size_t)x * 128 * kHID;
        Blo = g_Dlo + (size_t)y * kL * kHID + (size_t)x * 128 * kHID;
    } else {
        Ahi = g_Phi + (size_t)y * 128 * K;   Alo = g_Plo + (size_t)y * 128 * K;
        Bhi = g_Dhi + (size_t)y * kL * kHID; // [l][h], tile cols = x*128
        Blo = g_Dlo + (size_t)y * kL * kHID;
    }

    const int wm = (wid >> 1) * 32;       // warp M base
    const int wn = (wid & 1) * 64;        // warp N base

    auto load_stage = [&](int st, int k0) {
        const uint32_t so = sb + st * STG_BYTES;
#pragma unroll
        for (int it = 0; it < 4; ++it) {
            const int ch = tid + it * 256;
            {   // A tiles: 128 rows x 128B
                const int r = ch >> 3, c = ch & 7;
                const uint32_t d = sw128((uint32_t)(r * 128 + c * 16));
                const size_t go = (size_t)r * K + k0 + c * 8;
                cpa16(so + OFF_AHI + d, Ahi + go);
                cpa16(so + OFF_ALO + d, Alo + go);
            }
            if (MODE == 3) {   // B tile: 64 k-rows x 256B (n=128)
                const int r = ch >> 4, c = ch & 15;
                const uint32_t d = sw256((uint32_t)(r * 256 + c * 16));
                const size_t go = (size_t)(k0 + r) * kHID + x * 128 + c * 8;
                cpa16(so + OFF_BHI + d, Bhi + go);
                cpa16(so + OFF_BLO + d, Blo + go);
            } else {           // B tile: 128 n-rows x 128B
                const int r = ch >> 3, c = ch & 7;
                const uint32_t d = sw128((uint32_t)(r * 128 + c * 16));
                const size_t go = (size_t)r * K + k0 + c * 8;
                cpa16(so + OFF_BHI + d, Bhi + go);
                cpa16(so + OFF_BLO + d, Blo + go);
            }
        }
    };

    float acc[2][8][4] = {};

    constexpr int NCH = K / 64;
    load_stage(0, 0);
    cpa_commit();

    for (int kc = 0; kc < NCH; ++kc) {
        if (kc + 1 < NCH) load_stage((kc + 1) & 1, (kc + 1) * 64);
        cpa_commit();
        cpa_wait1();
        __syncthreads();

        const uint32_t so = sb + (kc & 1) * STG_BYTES;
#pragma unroll
        for (int kk = 0; kk < 4; ++kk) {      // k-steps of 16 bf16
            uint32_t aHi[2][4], aLo[2][4], bHi[8][2], bLo[8][2];
#pragma unroll
            for (int i = 0; i < 2; ++i) {
                const int row = wm + i * 16 + (lane & 15);
                const int kb  = kk * 32 + (lane >> 4) * 16;
                const uint32_t d = sw128((uint32_t)(row * 128 + kb));
                ldsm_x4(aHi[i], so + OFF_AHI + d);
                ldsm_x4(aLo[i], so + OFF_ALO + d);
            }
            if (MODE == 3) {
                // trans: smem [k][n], addresses per 8x8 quadrant
#pragma unroll
                for (int j4 = 0; j4 < 4; ++j4) {
                    const int row  = kk * 16 + ((lane >> 3) & 1) * 8 + (lane & 7);
                    const int colb = (wn + j4 * 16) * 2 + ((lane >> 4) & 1) * 16;
                    const uint32_t d = sw256((uint32_t)(row * 256 + colb));
                    uint32_t r4[4];
                    ldsm_x4_t(r4, so + OFF_BHI + d);
                    bHi[j4 * 2][0] = r4[0];     bHi[j4 * 2][1] = r4[1];
                    bHi[j4 * 2 + 1][0] = r4[2]; bHi[j4 * 2 + 1][1] = r4[3];
                    ldsm_x4_t(r4, so + OFF_BLO + d);
                    bLo[j4 * 2][0] = r4[0];     bLo[j4 * 2][1] = r4[1];
                    bLo[j4 * 2 + 1][0] = r4[2]; bLo[j4 * 2 + 1][1] = r4[3];
                }
            } else {
#pragma unroll
                for (int j4 = 0; j4 < 4; ++j4) {
                    const int row = wn + j4 * 16 + ((lane >> 4) & 1) * 8 + (lane & 7);
                    const int kb  = kk * 32 + ((lane >> 3) & 1) * 16;
                    const uint32_t d = sw128((uint32_t)(row * 128 + kb));
                    uint32_t r4[4];
                    ldsm_x4(r4, so + OFF_BHI + d);
                    bHi[j4 * 2][0] = r4[0];     bHi[j4 * 2][1] = r4[1];
                    bHi[j4 * 2 + 1][0] = r4[2]; bHi[j4 * 2 + 1][1] = r4[3];
                    ldsm_x4(r4, so + OFF_BLO + d);
                    bLo[j4 * 2][0] = r4[0];     bLo[j4 * 2][1] = r4[1];
                    bLo[j4 * 2 + 1][0] = r4[2]; bLo[j4 * 2 + 1][1] = r4[3];
                }
            }
#pragma unroll
            for (int i = 0; i < 2; ++i)
#pragma unroll
                for (int j = 0; j < 8; ++j) {
                    mma_bf16(acc[i][j], aHi[i], bHi[j]);
                    mma_bf16(acc[i][j], aHi[i], bLo[j]);
                    mma_bf16(acc[i][j], aLo[i], bHi[j]);
                }
        }
        __syncthreads();
    }

    // Epilogue. Thread holds rows (g, g+8), cols (2*t4, 2*t4+1) per mma tile.
    const int g = lane >> 2, t4 = lane & 3;
#pragma unroll
    for (int i = 0; i < 2; ++i) {
#pragma unroll
        for (int j = 0; j < 8; ++j) {
            const int r0 = wm + i * 16 + g;
            const int r1 = r0 + 8;
            const int cc = wn + j * 8 + 2 * t4;
            if (MODE == 1) {
                const size_t o0 = (size_t)(y * 128 + r0) * kHID + x * 128 + cc;
                const size_t o1 = (size_t)(y * 128 + r1) * kHID + x * 128 + cc;
                __nv_bfloat16 h0, l0, h1, l1;
                split2(acc[i][j][0], h0, l0); split2(acc[i][j][1], h1, l1);
                __nv_bfloat162 ph, pl;
                ph.x = h0; ph.y = h1; pl.x = l0; pl.y = l1;
                *(__nv_bfloat162*)(g_Qhi + o0) = ph;
                *(__nv_bfloat162*)(g_Qlo + o0) = pl;
                split2(acc[i][j][2], h0, l0); split2(acc[i][j][3], h1, l1);
                ph.x = h0; ph.y = h1; pl.x = l0; pl.y = l1;
                *(__nv_bfloat162*)(g_Qhi + o1) = ph;
                *(__nv_bfloat162*)(g_Qlo + o1) = pl;
            } else {
                float *o0, *o1;
                if (MODE == 2) {
                    o0 = g_P + (size_t)(y * 128 + r0) * kL + x * 128 + cc;
                    o1 = g_P + (size_t)(y * 128 + r1) * kL + x * 128 + cc;
                } else {
                    o0 = outP + (size_t)(y * 128 + r0) * kOut + kVEC + x * 128 + cc;
                    o1 = outP + (size_t)(y * 128 + r1) * kOut + kVEC + x * 128 + cc;
                }
                *(float2*)o0 = make_float2(acc[i][j][0], acc[i][j][1]);
                *(float2*)o1 = make_float2(acc[i][j][2], acc[i][j][3]);
            }
        }
    }
}

// ---------------------------------------------------------------------------
// Softmax over rows of g_P (8192 x 512) -> split bf16 attn g_Phi/g_Plo
// ---------------------------------------------------------------------------
__global__ void softmax_kernel() {
    const int lane = threadIdx.x & 31;
    const int warp = threadIdx.x >> 5;
    const int row = blockIdx.x * 8 + warp;
    const float4* p = (const float4*)(g_P + (size_t)row * kL);

    float4 v[4];
    float mx = -1e30f;
#pragma unroll
    for (int i = 0; i < 4; ++i) {
        v[i] = p[lane + 32 * i];
        mx = fmaxf(mx, fmaxf(fmaxf(v[i].x, v[i].y), fmaxf(v[i].z, v[i].w)));
    }
#pragma unroll
    for (int o = 16; o; o >>= 1) mx = fmaxf(mx, __shfl_xor_sync(0xffffffffu, mx, o));

    float sum = 0.f;
#pragma unroll
    for (int i = 0; i < 4; ++i) {
        v[i].x = __expf(v[i].x - mx); sum += v[i].x;
        v[i].y = __expf(v[i].y - mx); sum += v[i].y;
        v[i].z = __expf(v[i].z - mx); sum += v[i].z;
        v[i].w = __expf(v[i].w - mx); sum += v[i].w;
    }
#pragma unroll
    for (int o = 16; o; o >>= 1) sum += __shfl_xor_sync(0xffffffffu, sum, o);

    const float inv = 1.0f / sum;
#pragma unroll
    for (int i = 0; i < 4; ++i) {
        float e[4] = {v[i].x * inv, v[i].y * inv, v[i].z * inv, v[i].w * inv};
        size_t o = (size_t)row * kL + 4 * (lane + 32 * i);
        __nv_bfloat16 h0, h1, h2, h3, l0, l1, l2, l3;
        split2(e[0], h0, l0); split2(e[1], h1, l1);
        split2(e[2], h2, l2); split2(e[3], h3, l3);
        __nv_bfloat162 a;
        a.x = h0; a.y = h1; *(__nv_bfloat162*)(g_Phi + o) = a;
        a.x = h2; a.y = h3; *(__nv_bfloat162*)(g_Phi + o + 2) = a;
        a.x = l0; a.y = l1; *(__nv_bfloat162*)(g_Plo + o) = a;
        a.x = l2; a.y = l3; *(__nv_bfloat162*)(g_Plo + o + 2) = a;
    }
}

// ---------------------------------------------------------------------------
// Launch
// ---------------------------------------------------------------------------
extern "C" void kernel_launch(void* const* d_in, const int* in_sizes, int n_in,
                              void* d_out, int out_size) {
    (void)in_sizes; (void)n_in; (void)out_size;
    const int*   s32  = (const int*)d_in[0];
    const float* desc = (const float*)d_in[1];
    const float* emb  = (const float*)d_in[2];
    const float* W    = (const float*)d_in[3];
    float* out = (float*)d_out;

    cudaFuncSetAttribute(mma_gemm<1>, cudaFuncAttributeMaxDynamicSharedMemorySize, SMEM_BYTES);
    cudaFuncSetAttribute(mma_gemm<2>, cudaFuncAttributeMaxDynamicSharedMemorySize, SMEM_BYTES);
    cudaFuncSetAttribute(mma_gemm<3>, cudaFuncAttributeMaxDynamicSharedMemorySize, SMEM_BYTES);

    probe_kernel<<<1, 1>>>(s32);
    conv_sk<<<kRows, 128>>>(s32, emb, out);
    conv_desc<<<(kB * kL * kHID) / (256 * 4), 256>>>(desc);
    conv_W<<<dim3(kHID / 32, kVEC / 32), dim3(32, 8)>>>(W);

    // GEMM1: Q[8192,1024]
    mma_gemm<1><<<dim3(kHID / 128, kRows / 128), 256, SMEM_BYTES>>>(nullptr);
    // GEMM2: scores[b][128,512]
    mma_gemm<2><<<dim3(kL / 128, kB), 256, SMEM_BYTES>>>(nullptr);
    softmax_kernel<<<kRows / 8, 256>>>();
    // GEMM3: ctx[b][128,1024]
    mma_gemm<3><<<dim3(kHID / 128, kB), 256, SMEM_BYTES>>>(out);
}